// round 12
// baseline (speedup 1.0000x reference)
#include <cuda_runtime.h>
#include <cuda_fp16.h>
#include <cstdint>
#include <cstddef>

static constexpr int NN = 50000;   // nodes
static constexpr int NE = 800000;  // edges
// features: 128 -> 256 -> 128

// ---------------- scratch (device globals; no allocation allowed) -----------
__device__ int    g_is64;                    // edge_index dtype flag
__device__ int    g_cnt[NN];                 // in-degree (no self-loop)
__device__ int    g_cur[NN];                 // fill cursors
__device__ int    g_row[NN];                 // CSR row starts
__device__ int    g_csr[NE];                 // CSR src indices
__device__ float  g_isd[NN];                 // 1/sqrt(deg), deg incl self-loop
__device__ __half g_xh[(size_t)NN * 128];    // x in fp16 (gather source, L1)
__device__ float  g_ax[(size_t)NN * 128];    // A_norm @ x
__device__ float  g_z1[(size_t)NN * 256];    // relu(ax @ W1 + b1)
__device__ __half g_t2h[(size_t)NN * 128];   // z1 @ W2 in fp16 (gather source, L2)

// ---------------- edge_index dtype probe -------------------------------------
__global__ void k_detect(const void* __restrict__ ei) {
    __shared__ int bad;
    if (threadIdx.x == 0) bad = 0;
    __syncthreads();
    const long long* p = (const long long*)ei;
    for (int i = threadIdx.x; i < 1024; i += blockDim.x) {
        long long v = p[i];
        if (v < 0 || v >= NN) bad = 1;
    }
    __syncthreads();
    if (threadIdx.x == 0) g_is64 = bad ? 0 : 1;
}

__device__ __forceinline__ int edge_at(const void* __restrict__ ei, int idx) {
    if (g_is64) return (int)((const long long*)ei)[idx];
    return ((const int*)ei)[idx];
}

// ---------------- init: counters + x -> fp16 conversion (fused) --------------
__global__ void k_init(const float* __restrict__ x) {
    int i = blockIdx.x * blockDim.x + threadIdx.x;
    if (i < NN) { g_cnt[i] = 0; g_cur[i] = 0; }
    if (i < NN * 32) {                       // NN*128/4 float4 chunks
        float4 v = ((const float4*)x)[i];
        __half2 h0 = __floats2half2_rn(v.x, v.y);
        __half2 h1 = __floats2half2_rn(v.z, v.w);
        uint2 u;
        u.x = *(uint32_t*)&h0;
        u.y = *(uint32_t*)&h1;
        ((uint2*)g_xh)[i] = u;
    }
}

__global__ void k_count(const void* __restrict__ ei) {
    int e = blockIdx.x * blockDim.x + threadIdx.x;
    if (e < NE) atomicAdd(&g_cnt[edge_at(ei, NE + e)], 1);
}

__global__ void k_isd() {
    int i = blockIdx.x * blockDim.x + threadIdx.x;
    if (i < NN) g_isd[i] = rsqrtf(1.0f + (float)g_cnt[i]);
}

__global__ void __launch_bounds__(1024) k_scan() {
    __shared__ int sh[2][1024];
    const int t  = threadIdx.x;
    const int CH = (NN + 1023) / 1024;   // 49
    const int b0 = t * CH;

    int local = 0;
    for (int i = 0; i < CH; i++) {
        int idx = b0 + i;
        if (idx < NN) local += g_cnt[idx];
    }
    int cur = 0;
    sh[cur][t] = local;
    __syncthreads();
    for (int off = 1; off < 1024; off <<= 1) {
        int nxt = cur ^ 1;
        int v = sh[cur][t];
        if (t >= off) v += sh[cur][t - off];
        sh[nxt][t] = v;
        __syncthreads();
        cur = nxt;
    }
    int run = (t == 0) ? 0 : sh[cur][t - 1];
    for (int i = 0; i < CH; i++) {
        int idx = b0 + i;
        if (idx < NN) { g_row[idx] = run; run += g_cnt[idx]; }
    }
}

__global__ void k_fill(const void* __restrict__ ei) {
    int e = blockIdx.x * blockDim.x + threadIdx.x;
    if (e >= NE) return;
    int s = edge_at(ei, e);
    int d = edge_at(ei, NE + e);
    int pos = g_row[d] + atomicAdd(&g_cur[d], 1);
    g_csr[pos] = s;
}

// ---------------- fp16 gather core: 2-way unroll, fp32 accumulate ------------
// Each lane covers features [lane*4, lane*4+4): one 8 B load per row.
__device__ __forceinline__ float4 gather_rows_h(const __half* __restrict__ h,
                                                int node, int lane, float sd,
                                                float4 acc) {
    const int beg = g_row[node];
    const int cnt = g_cnt[node];
    int e = 0;
    for (; e + 2 <= cnt; e += 2) {
        int s0 = g_csr[beg + e];
        int s1 = g_csr[beg + e + 1];
        float n0 = sd * g_isd[s0];
        float n1 = sd * g_isd[s1];
        uint2 ua = *(const uint2*)(h + (size_t)s0 * 128 + lane * 4);
        uint2 ub = *(const uint2*)(h + (size_t)s1 * 128 + lane * 4);
        float2 a0 = __half22float2(*(__half2*)&ua.x);
        float2 a1 = __half22float2(*(__half2*)&ua.y);
        float2 b0 = __half22float2(*(__half2*)&ub.x);
        float2 b1 = __half22float2(*(__half2*)&ub.y);
        acc.x += a0.x * n0 + b0.x * n1;
        acc.y += a0.y * n0 + b0.y * n1;
        acc.z += a1.x * n0 + b1.x * n1;
        acc.w += a1.y * n0 + b1.y * n1;
    }
    if (e < cnt) {
        int s0 = g_csr[beg + e];
        float n0 = sd * g_isd[s0];
        uint2 ua = *(const uint2*)(h + (size_t)s0 * 128 + lane * 4);
        float2 a0 = __half22float2(*(__half2*)&ua.x);
        float2 a1 = __half22float2(*(__half2*)&ua.y);
        acc.x += a0.x * n0; acc.y += a0.y * n0;
        acc.z += a1.x * n0; acc.w += a1.y * n0;
    }
    return acc;
}

// ---------------- aggregation 1: ax = A_norm @ x (128 feat) ------------------
__global__ void __launch_bounds__(256)
k_aggX(const float* __restrict__ x) {
    const int warp = threadIdx.x >> 5;
    const int lane = threadIdx.x & 31;
    const int node = blockIdx.x * 8 + warp;
    if (node >= NN) return;

    const float sd = g_isd[node];
    float4 t = ((const float4*)(x + (size_t)node * 128))[lane];   // fp32 self-loop
    const float w = sd * sd;
    float4 acc = make_float4(t.x * w, t.y * w, t.z * w, t.w * w);

    acc = gather_rows_h(g_xh, node, lane, sd, acc);

    ((float4*)(g_ax + (size_t)node * 128))[lane] = acc;
}

// ---------------- tf32 tensor-core GEMM, cp.async double-buffered ------------
__device__ __forceinline__ uint32_t f2tf32(float f) {
    uint32_t o;
    asm("cvt.rna.tf32.f32 %0, %1;" : "=r"(o) : "f"(f));
    return o;
}

__device__ __forceinline__ void mma_tf32(float c[4], const uint32_t a[4],
                                         const uint32_t b[2]) {
    asm volatile(
        "mma.sync.aligned.m16n8k8.row.col.f32.tf32.tf32.f32 "
        "{%0,%1,%2,%3}, {%4,%5,%6,%7}, {%8,%9}, {%0,%1,%2,%3};"
        : "+f"(c[0]), "+f"(c[1]), "+f"(c[2]), "+f"(c[3])
        : "r"(a[0]), "r"(a[1]), "r"(a[2]), "r"(a[3]),
          "r"(b[0]), "r"(b[1]));
}

__device__ __forceinline__ void cp16(void* s, const void* g) {
    uint32_t sa = (uint32_t)__cvta_generic_to_shared(s);
    asm volatile("cp.async.cg.shared.global [%0], [%1], 16;"
                 :: "r"(sa), "l"(g) : "memory");
}

static constexpr int GBM = 128, GBN = 64, GBK = 32;
static constexpr int GLDA = GBK + 4;
static constexpr int GLDB = GBN + 8;
static constexpr int AS_SZ = GBM * GLDA;
static constexpr int BS_SZ = GBK * GLDB;
static constexpr int GEMM_SMEM = 2 * (AS_SZ + BS_SZ) * 4;   // 55296 B

template <bool L1>
__global__ void __launch_bounds__(256)
tgemm(const float* __restrict__ W, const float* __restrict__ bias) {
    constexpr int K  = L1 ? 128 : 256;
    constexpr int N  = L1 ? 256 : 128;
    constexpr int KT = K / GBK;

    const float* __restrict__ A = L1 ? g_ax : g_z1;

    extern __shared__ float smem[];
    float* As = smem;
    float* Bs = smem + 2 * AS_SZ;

    const int tid  = threadIdx.x;
    const int lane = tid & 31;
    const int wid  = tid >> 5;
    const int wm   = wid & 3;
    const int wn   = wid >> 2;
    const int gID  = lane >> 2;
    const int tg   = lane & 3;

    const int bm0 = blockIdx.y * GBM;
    const int bn0 = blockIdx.x * GBN;

    float c[2][4][4] = {};

    auto stage = [&](int kt, int buf) {
        float* as = As + buf * AS_SZ;
        float* bs = Bs + buf * BS_SZ;
        #pragma unroll
        for (int i = 0; i < 4; i++) {
            int idx = tid + i * 256;
            int r   = idx >> 3;
            int c4  = (idx & 7) * 4;
            int rg  = min(bm0 + r, NN - 1);
            cp16(&as[r * GLDA + c4], A + (size_t)rg * K + kt * GBK + c4);
        }
        #pragma unroll
        for (int i = 0; i < 2; i++) {
            int idx = tid + i * 256;
            int r   = idx >> 4;
            int c4  = (idx & 15) * 4;
            cp16(&bs[r * GLDB + c4], W + (size_t)(kt * GBK + r) * N + bn0 + c4);
        }
        asm volatile("cp.async.commit_group;" ::: "memory");
    };

    stage(0, 0);
    for (int kt = 0; kt < KT; kt++) {
        int buf = kt & 1;
        if (kt + 1 < KT) {
            stage(kt + 1, buf ^ 1);
            asm volatile("cp.async.wait_group 1;" ::: "memory");
        } else {
            asm volatile("cp.async.wait_group 0;" ::: "memory");
        }
        __syncthreads();

        const float* as = As + buf * AS_SZ;
        const float* bs = Bs + buf * BS_SZ;
        #pragma unroll
        for (int kk = 0; kk < GBK / 8; kk++) {
            uint32_t a[2][4], b[4][2];
            #pragma unroll
            for (int mi = 0; mi < 2; mi++) {
                int rb = wm * 32 + mi * 16 + gID;
                int kb = kk * 8 + tg;
                a[mi][0] = f2tf32(as[rb * GLDA + kb]);
                a[mi][1] = f2tf32(as[(rb + 8) * GLDA + kb]);
                a[mi][2] = f2tf32(as[rb * GLDA + kb + 4]);
                a[mi][3] = f2tf32(as[(rb + 8) * GLDA + kb + 4]);
            }
            #pragma unroll
            for (int ni = 0; ni < 4; ni++) {
                int col = wn * 32 + ni * 8 + gID;
                int kb  = kk * 8 + tg;
                b[ni][0] = f2tf32(bs[kb * GLDB + col]);
                b[ni][1] = f2tf32(bs[(kb + 4) * GLDB + col]);
            }
            #pragma unroll
            for (int mi = 0; mi < 2; mi++)
                #pragma unroll
                for (int ni = 0; ni < 4; ni++)
                    mma_tf32(c[mi][ni], a[mi], b[ni]);
        }
        __syncthreads();
    }

    #pragma unroll
    for (int mi = 0; mi < 2; mi++) {
        int r0 = bm0 + wm * 32 + mi * 16 + gID;
        #pragma unroll
        for (int ni = 0; ni < 4; ni++) {
            int col = bn0 + wn * 32 + ni * 8 + tg * 2;
            float2 v0 = make_float2(c[mi][ni][0], c[mi][ni][1]);
            float2 v1 = make_float2(c[mi][ni][2], c[mi][ni][3]);
            if (L1) {
                // bias + relu, fp32 store to g_z1
                float bx = bias[col], by = bias[col + 1];
                v0.x = fmaxf(v0.x + bx, 0.f); v0.y = fmaxf(v0.y + by, 0.f);
                v1.x = fmaxf(v1.x + bx, 0.f); v1.y = fmaxf(v1.y + by, 0.f);
                if (r0 < NN)
                    *(float2*)(g_z1 + (size_t)r0 * N + col) = v0;
                if (r0 + 8 < NN)
                    *(float2*)(g_z1 + (size_t)(r0 + 8) * N + col) = v1;
            } else {
                // raw fp16 store to g_t2h (gather source for layer-2 agg)
                __half2 h0 = __floats2half2_rn(v0.x, v0.y);
                __half2 h1 = __floats2half2_rn(v1.x, v1.y);
                if (r0 < NN)
                    *(__half2*)(g_t2h + (size_t)r0 * N + col) = h0;
                if (r0 + 8 < NN)
                    *(__half2*)(g_t2h + (size_t)(r0 + 8) * N + col) = h1;
            }
        }
    }
}

// ---------------- aggregation 2 + bias + relu + pool + fc --------------------
__global__ void __launch_bounds__(256)
k_agg2(const float* __restrict__ bias, const float* __restrict__ Wfc,
       float* __restrict__ out) {
    const int warp = threadIdx.x >> 5;
    const int lane = threadIdx.x & 31;
    const int node = blockIdx.x * 8 + warp;
    if (node >= NN) return;

    const float sd = g_isd[node];
    // self-loop from fp16 t2
    uint2 ut = *(const uint2*)(g_t2h + (size_t)node * 128 + lane * 4);
    float2 t0 = __half22float2(*(__half2*)&ut.x);
    float2 t1 = __half22float2(*(__half2*)&ut.y);
    const float w = sd * sd;
    float4 acc = make_float4(t0.x * w, t0.y * w, t1.x * w, t1.y * w);

    acc = gather_rows_h(g_t2h, node, lane, sd, acc);

    float4 bb = ((const float4*)bias)[lane];
    float4 wf = ((const float4*)Wfc)[lane];
    float dot =
        fmaxf(acc.x + bb.x, 0.f) * wf.x +
        fmaxf(acc.y + bb.y, 0.f) * wf.y +
        fmaxf(acc.z + bb.z, 0.f) * wf.z +
        fmaxf(acc.w + bb.w, 0.f) * wf.w;

    #pragma unroll
    for (int o = 16; o; o >>= 1) dot += __shfl_down_sync(0xffffffffu, dot, o);
    if (lane == 0) atomicAdd(out, dot * (1.0f / NN));
}

__global__ void k_out_init(const float* __restrict__ bfc, float* __restrict__ out) {
    out[0] = bfc[0];
}

// ---------------- launch ------------------------------------------------------
extern "C" void kernel_launch(void* const* d_in, const int* in_sizes, int n_in,
                              void* d_out, int out_size) {
    const float* x   = (const float*)d_in[0];
    const void*  ei  = d_in[1];                 // int32 or int64 — probed on device
    const float* W1  = (const float*)d_in[2];
    const float* b1  = (const float*)d_in[3];
    const float* W2  = (const float*)d_in[4];
    const float* b2  = (const float*)d_in[5];
    const float* Wfc = (const float*)d_in[6];
    const float* bfc = (const float*)d_in[7];
    float* out = (float*)d_out;
    (void)in_sizes; (void)n_in; (void)out_size;

    cudaFuncSetAttribute(tgemm<true>,
        cudaFuncAttributeMaxDynamicSharedMemorySize, GEMM_SMEM);
    cudaFuncSetAttribute(tgemm<false>,
        cudaFuncAttributeMaxDynamicSharedMemorySize, GEMM_SMEM);

    // dtype probe + CSR build (+ fused x->fp16 conversion in k_init)
    k_detect<<<1, 256>>>(ei);
    k_init  <<<(NN * 32 + 255) / 256, 256>>>(x);
    k_count <<<(NE + 255) / 256, 256>>>(ei);
    k_isd   <<<(NN + 255) / 256, 256>>>();
    k_scan  <<<1, 1024>>>();
    k_fill  <<<(NE + 255) / 256, 256>>>(ei);

    // layer 1: aggregate x first (fp16 gather), then fused GEMM+bias+relu
    k_aggX<<<(NN + 7) / 8, 256>>>(x);
    tgemm<true><<<dim3(256 / 64, (NN + 127) / 128), 256, GEMM_SMEM>>>(W1, b1);

    // layer 2: transform first (fp16 epilogue), then fused agg+bias+relu+pool+fc
    tgemm<false><<<dim3(128 / 64, (NN + 127) / 128), 256, GEMM_SMEM>>>(W2, nullptr);
    k_out_init<<<1, 1>>>(bfc, out);
    k_agg2<<<(NN + 7) / 8, 256>>>(b2, Wfc, out);
}